// round 6
// baseline (speedup 1.0000x reference)
#include <cuda_runtime.h>
#include <cuda_bf16.h>

// y[b] = sum over segments s=0..21 of w[s]*f_s; f_s picks the highest-m valid
// candidate (m, l=s-3m) with x[m] in (phi-iv[m], phi+iv[m]], value
// 0.5*cos(x[m]-phi)+0.5. Per row:
//   y = C0 cos x0 + S0 sin x0 + C1 cos x1 + S1 sin x1 + C2 cos x2 + S2 sin x2 + T
// Coefficients depend only on the rank triple (r0,r1,r2) of x[m] among each
// m's 32 sorted window bounds. Split by dependency:
//   (C2,S2,T2) = f(r2)        -> 33-entry smem table
//   (C1,S1,T1) = f(r1,r2)     -> 1089-entry smem table (staged per block)
//   (C0,S0,T0) = f(r0,r1,r2)  -> 33^3-entry L2 table, 16B entry = 1 sector
// Output: [ y (batch floats), weight (48 floats) ].

#define TPB 256
#define RPT 8
#define NR   33
#define NPAIR (NR * NR)       // 1089
#define NTAB  (NR * NR * NR)  // 35937

__device__ float  gSortedB[96];     // [m*32 + pos]
__device__ float4 gTrip[NTAB];      // (C0,S0,T0,0) indexed by (r0*33+r1)*33+r2
__device__ float4 gPair[NPAIR];     // (C1,S1,T1,0) indexed by r1*33+r2
__device__ float4 gSingle[NR];      // (C2,S2,T2,0) indexed by r2

// ---------------- fused setup: every block recomputes masks, fills a slice --
__global__ void __launch_bounds__(TPB)
setup_all(const float* __restrict__ phis,
          const float* __restrict__ interval,
          const float* __restrict__ weight) {
    __shared__ float    sv[96];
    __shared__ int      spos[96];
    __shared__ float    svc[3][3][16];   // [m][{c,s,t}][l]
    __shared__ unsigned sSH[3][NR];

    const int t = threadIdx.x;

    if (t < 96) {
        const int m = t >> 5, i = t & 31, l = i & 15;
        const float p  = phis[m * 16 + l];
        const float iv = interval[m];
        sv[t] = (i < 16) ? (p - iv) : (p + iv);
    }
    if (t < 48) {
        const int m = t >> 4, l = t & 15;
        const float w = 0.5f * weight[3 * m + l];    // segment s = 3m + l
        const float p = phis[m * 16 + l];
        float sp, cp;
        sincosf(p, &sp, &cp);
        svc[m][0][l] = w * cp;
        svc[m][1][l] = w * sp;
        svc[m][2][l] = w;
    }
    __syncthreads();

    // stable rank-sort of each m's 32 bounds
    if (t < 96) {
        const int m = t >> 5, i = t & 31;
        const float v = sv[t];
        int pos = 0;
        for (int j = 0; j < 32; ++j) {
            const float u = sv[(m << 5) + j];
            pos += (u < v || (u == v && j < i)) ? 1 : 0;
        }
        spos[t] = pos;
        if (blockIdx.x == 0) gSortedB[(m << 5) + pos] = v;
    }
    __syncthreads();

    // hitmask per rank r: cond_l <=> pos(lo_l) < r && pos(hi_l) >= r
    if (t < 3 * NR) {
        const int m = t / NR, r = t - m * NR;
        unsigned mask = 0;
        for (int l = 0; l < 16; ++l) {
            const int plo  = spos[(m << 5) + l];
            const int phi_ = spos[(m << 5) + 16 + l];
            if (plo < r && phi_ >= r) mask |= (1u << l);
        }
        sSH[m][r] = mask << (3 * m);   // segment space
    }
    __syncthreads();

    if (blockIdx.x == 0) {
        // single table: W2 = H2
        if (t < NR) {
            const unsigned W2 = sSH[2][t];
            float C = 0.f, S = 0.f, T = 0.f;
            for (int l = 0; l < 16; ++l)
                if (W2 & (1u << (6 + l))) { C += svc[2][0][l]; S += svc[2][1][l]; T += svc[2][2][l]; }
            gSingle[t] = make_float4(C, S, T, 0.0f);
        }
        // pair table: W1 = H1 & ~H2
        for (int e = t; e < NPAIR; e += TPB) {
            const int r1 = e / NR, r2 = e - r1 * NR;
            const unsigned W1 = sSH[1][r1] & ~sSH[2][r2];
            float C = 0.f, S = 0.f, T = 0.f;
            for (int l = 0; l < 16; ++l)
                if (W1 & (1u << (3 + l))) { C += svc[1][0][l]; S += svc[1][1][l]; T += svc[1][2][l]; }
            gPair[e] = make_float4(C, S, T, 0.0f);
        }
    }

    // triple table: W0 = H0 & ~H1 & ~H2
    for (int e = blockIdx.x * TPB + t; e < NTAB; e += gridDim.x * TPB) {
        const int r0  = e / NPAIR;
        const int rem = e - r0 * NPAIR;
        const int r1  = rem / NR;
        const int r2  = rem - r1 * NR;
        const unsigned W0 = sSH[0][r0] & ~sSH[1][r1] & ~sSH[2][r2];
        float C = 0.f, S = 0.f, T = 0.f;
        for (int l = 0; l < 16; ++l)
            if (W0 & (1u << l)) { C += svc[0][0][l]; S += svc[0][1][l]; T += svc[0][2][l]; }
        gTrip[e] = make_float4(C, S, T, 0.0f);
    }
}

// ---------------- main ------------------------------------------------------
// rank = #{bounds < x} in [0,32]; first two pivots come from registers.
__device__ __forceinline__ int rank32r(const float* __restrict__ b,
                                       float b7, float b15, float b23, float xv) {
    int r = (b15 < xv) ? 16 : 0;
    const float p2 = (b15 < xv) ? b23 : b7;   // b[r+7]
    if (p2       < xv) r += 8;
    if (b[r + 3] < xv) r += 4;
    if (b[r + 1] < xv) r += 2;
    if (b[r]     < xv) r += 1;
    if (b[r]     < xv) r += 1;
    return r;
}

__global__ void __launch_bounds__(TPB)
glm_main(const float* __restrict__ x,
         const float* __restrict__ weight,
         float* __restrict__ out, int batch) {
    __shared__ float  sb[96];
    __shared__ float4 sPair[NPAIR];
    __shared__ float4 sSingle[NR];

    const int t = threadIdx.x;
    if (t < 96) sb[t] = gSortedB[t];
    if (t < NR) sSingle[t] = gSingle[t];
    for (int i = t; i < NPAIR; i += TPB) sPair[i] = gPair[i];
    if (blockIdx.x == 0 && t < 48) out[batch + t] = weight[t];  // weight tail
    __syncthreads();

    const int tid = blockIdx.x * TPB + t;
    const long long row0 = (long long)tid * RPT;
    if (row0 >= batch) return;

    // 8 rows * 3 floats = 96B = 6 x float4
    const float4* xv = reinterpret_cast<const float4*>(x + row0 * 3);
    const float4 v0 = xv[0], v1 = xv[1], v2 = xv[2];
    const float4 v3 = xv[3], v4 = xv[4], v5 = xv[5];
    const float X[RPT][3] = {
        {v0.x, v0.y, v0.z}, {v0.w, v1.x, v1.y},
        {v1.z, v1.w, v2.x}, {v2.y, v2.z, v2.w},
        {v3.x, v3.y, v3.z}, {v3.w, v4.x, v4.y},
        {v4.z, v4.w, v5.x}, {v5.y, v5.z, v5.w}
    };

    // register-cached pivots per m
    const float a7  = sb[7],  a15 = sb[15], a23 = sb[23];
    const float b7  = sb[39], b15 = sb[47], b23 = sb[55];
    const float c7  = sb[71], c15 = sb[79], c23 = sb[87];

    float Y[RPT];
#pragma unroll
    for (int r = 0; r < RPT; ++r) {
        const int ra = rank32r(sb,      a7, a15, a23, X[r][0]);
        const int rb = rank32r(sb + 32, b7, b15, b23, X[r][1]);
        const int rc = rank32r(sb + 64, c7, c15, c23, X[r][2]);
        const float4 tv = __ldg(&gTrip[(ra * NR + rb) * NR + rc]);  // 1 sector
        const float4 pv = sPair[rb * NR + rc];
        const float4 sv2 = sSingle[rc];
        float s0, c0, s1, c1, s2, c2;
        __sincosf(X[r][0], &s0, &c0);
        __sincosf(X[r][1], &s1, &c1);
        __sincosf(X[r][2], &s2, &c2);
        float y = (tv.z + pv.z) + sv2.z;
        y = fmaf(c0, tv.x, y);  y = fmaf(s0, tv.y, y);
        y = fmaf(c1, pv.x, y);  y = fmaf(s1, pv.y, y);
        y = fmaf(c2, sv2.x, y); y = fmaf(s2, sv2.y, y);
        Y[r] = y;
    }

    float4* op = reinterpret_cast<float4*>(out);
    op[2 * tid]     = make_float4(Y[0], Y[1], Y[2], Y[3]);
    op[2 * tid + 1] = make_float4(Y[4], Y[5], Y[6], Y[7]);
}

extern "C" void kernel_launch(void* const* d_in, const int* in_sizes, int n_in,
                              void* d_out, int out_size) {
    const float* x        = (const float*)d_in[0];
    const float* phis     = (const float*)d_in[1];
    const float* interval = (const float*)d_in[2];
    const float* weight   = (const float*)d_in[3];
    float* out = (float*)d_out;

    const int batch = in_sizes[0] / 3;
    const int n_threads = (batch + RPT - 1) / RPT;
    const int n_blocks  = (n_threads + TPB - 1) / TPB;

    setup_all<<<(NTAB + TPB - 1) / TPB, TPB>>>(phis, interval, weight);
    glm_main<<<n_blocks, TPB>>>(x, weight, out, batch);
}